// round 4
// baseline (speedup 1.0000x reference)
#include <cuda_runtime.h>
#include <cuda_bf16.h>
#include <cstdint>

// Inputs (metadata order):
// 0: hidden_states [B, ITEM] f32
// 1: actions       [B]       i32   (UNUSED by reference)
// 2: rewards       [B]       f32
// 3: discount      []        f32 (scalar, 1 element)
// 4: targetQs_s    [B, ITEM] f32
// 5: is_done       [B]       bool (uint8)
// 6: W             [1, ITEM] f32
// 7: b             [1]       f32
// out: scalar f32

__global__ void zero_out_kernel(float* out) {
    if (threadIdx.x == 0) out[0] = 0.0f;
}

__global__ __launch_bounds__(256, 8)
void dqn_loss_kernel(const float4* __restrict__ hs,
                     const float4* __restrict__ tq,
                     const float4* __restrict__ W4,
                     const float*  __restrict__ rewards,
                     const float*  __restrict__ discount,
                     const unsigned char* __restrict__ is_done,
                     const float*  __restrict__ bias,
                     float* __restrict__ out,
                     int nvec,        // ITEM / 4
                     int item,        // ITEM
                     float invB)
{
    const int row = blockIdx.x;
    const int tid = threadIdx.x;
    const size_t base = (size_t)row * (size_t)nvec;
    const float4* __restrict__ h = hs + base;
    const float4* __restrict__ t = tq + base;

    float q = 0.0f, nq = 0.0f;

    // Main vectorized streaming loop: two 128-bit HBM loads + one L2-resident
    // W load per iteration. Unroll 4 so ptxas front-batches 8 independent
    // global loads per group (MLP_eff ~8) and keeps the LSU queue full.
    #pragma unroll 4
    for (int i = tid; i < nvec; i += blockDim.x) {
        float4 w = __ldg(&W4[i]);
        float4 a = __ldg(&h[i]);
        float4 c = __ldg(&t[i]);
        q  = fmaf(a.x, w.x, q);  q  = fmaf(a.y, w.y, q);
        q  = fmaf(a.z, w.z, q);  q  = fmaf(a.w, w.w, q);
        nq = fmaf(c.x, w.x, nq); nq = fmaf(c.y, w.y, nq);
        nq = fmaf(c.z, w.z, nq); nq = fmaf(c.w, w.w, nq);
    }

    // Scalar tail (ITEM % 4 != 0). Empty for ITEM=10000.
    int tail_start = nvec * 4;
    const float* hsc = (const float*)hs + (size_t)row * item;
    const float* tsc = (const float*)tq + (size_t)row * item;
    const float* wsc = (const float*)W4;
    for (int i = tail_start + tid; i < item; i += blockDim.x) {
        float w = __ldg(&wsc[i]);
        q  = fmaf(__ldg(&hsc[i]), w, q);
        nq = fmaf(__ldg(&tsc[i]), w, nq);
    }

    // Warp reduction
    #pragma unroll
    for (int off = 16; off > 0; off >>= 1) {
        q  += __shfl_down_sync(0xFFFFFFFFu, q,  off);
        nq += __shfl_down_sync(0xFFFFFFFFu, nq, off);
    }

    __shared__ float sq[8], snq[8];
    const int wid = tid >> 5;
    const int lid = tid & 31;
    if (lid == 0) { sq[wid] = q; snq[wid] = nq; }
    __syncthreads();

    if (wid == 0) {
        const int nwarps = blockDim.x >> 5;
        float vq  = (lid < nwarps) ? sq[lid]  : 0.0f;
        float vnq = (lid < nwarps) ? snq[lid] : 0.0f;
        #pragma unroll
        for (int off = 4; off > 0; off >>= 1) {
            vq  += __shfl_down_sync(0xFFFFFFFFu, vq,  off);
            vnq += __shfl_down_sync(0xFFFFFFFFu, vnq, off);
        }
        if (lid == 0) {
            float b0 = __ldg(bias);
            float g  = __ldg(discount);
            float Q  = fmaxf(vq  + b0, 0.0f);
            float NQ = fmaxf(vnq + b0, 0.0f);
            float per = fabsf(__ldg(&rewards[row]) + g * NQ - Q);
            if (is_done[row]) per = 0.0f;
            atomicAdd(out, per * invB);
        }
    }
}

extern "C" void kernel_launch(void* const* d_in, const int* in_sizes, int n_in,
                              void* d_out, int out_size)
{
    const float* hidden   = (const float*)d_in[0];
    // d_in[1] = actions (unused)
    const float* rewards  = (const float*)d_in[2];
    const float* discount = (const float*)d_in[3];
    const float* targetQ  = (const float*)d_in[4];
    const unsigned char* is_done = (const unsigned char*)d_in[5];
    const float* W        = (const float*)d_in[6];
    const float* bias     = (const float*)d_in[7];
    float* out            = (float*)d_out;

    const int B    = in_sizes[2];            // rewards element count
    const int ITEM = in_sizes[0] / B;        // 10000
    const int nvec = ITEM / 4;               // 2500
    const float invB = 1.0f / (float)B;

    zero_out_kernel<<<1, 32>>>(out);
    dqn_loss_kernel<<<B, 256>>>((const float4*)hidden,
                                (const float4*)targetQ,
                                (const float4*)W,
                                rewards, discount, is_done, bias,
                                out, nvec, ITEM, invB);
}